// round 8
// baseline (speedup 1.0000x reference)
#include <cuda_runtime.h>
#include <cuda_bf16.h>
#include <cstdint>

// ============================================================================
// BilinearChebConv via mma.sync bf16-split GEMMs (compute_103-safe PTX only).
//
// out[o] = sum_{i,j} theta[i,j,o] * (Tr_i @ X @ Tc_j) + bias,
// Tr/Tc = Chebyshev bases of symmetric Lr/Lc (order 4), M = N = 1536.
//
// Every 1536^3 GEMM runs on tensor cores (mma.sync m16n8k16 bf16->fp32) with a
// 2-term bf16 split: A@B ~= Ah@Bh + Ah@Bl + Al@Bh  (error ~2^-17 per product).
// All Chebyshev matrices are symmetric => B^T = B, so both operands are fed
// K-major. Only X needs a one-time transpose (B operand of stage B).
//
// R8 = proven R6 core (256 thr, 8 warps, 2x8 frags, 2-stage cp.async) with:
//   - product loop reordered p-outer: 16 independent MMA chains issued
//     back-to-back (asm volatile blocked compiler reordering in R6, so the
//     3 same-accumulator MMAs serialized on RAW latency)
//   - BK 32 -> 64: half the barrier/wait events
//   - hoisted ldmatrix offsets
// ============================================================================

#define MM 1536
#define PLANE ((size_t)MM * MM)

#define BM 128
#define BN 128
#define BK 64
#define NCH (MM / BK)               // 24 k-chunks
#define ROWB 144                    // 64 bf16 = 128B data + 16B pad
#define TILEB (128 * ROWB)          // 18432 B per matrix tile
#define STAGEB (4 * TILEB)          // Ah, Al, Bh, Bl = 73728 B
#define SMEM_TOTAL (2 * STAGEB)     // double buffered: 147456 B

// ---------------------------------------------------------------------------
// Scratch (device globals; no runtime allocation)
// ---------------------------------------------------------------------------
__device__ __nv_bfloat16 g_Trh[4 * (size_t)MM * MM];
__device__ __nv_bfloat16 g_Trl[4 * (size_t)MM * MM];
__device__ __nv_bfloat16 g_Tch[4 * (size_t)MM * MM];
__device__ __nv_bfloat16 g_Tcl[4 * (size_t)MM * MM];
__device__ __nv_bfloat16 g_Xh [(size_t)MM * MM];
__device__ __nv_bfloat16 g_Xl [(size_t)MM * MM];
__device__ __nv_bfloat16 g_Xth[(size_t)MM * MM];
__device__ __nv_bfloat16 g_Xtl[(size_t)MM * MM];
__device__ float         g_Yf[4 * (size_t)MM * MM];
__device__ __nv_bfloat16 g_Yh[4 * (size_t)MM * MM];
__device__ __nv_bfloat16 g_Yl[4 * (size_t)MM * MM];
__device__ float g_T2f[2 * (size_t)MM * MM];
__device__ float g_Z[20 * (size_t)MM * MM];

// ---------------------------------------------------------------------------
// PTX helpers (all valid on plain compute_103)
// ---------------------------------------------------------------------------
__device__ __forceinline__ uint32_t smem_u32(const void* p) {
    uint32_t a;
    asm("{ .reg .u64 t; cvta.to.shared.u64 t, %1; cvt.u32.u64 %0, t; }"
        : "=r"(a) : "l"(p));
    return a;
}

__device__ __forceinline__ void cp16(uint32_t dst, const void* src) {
    asm volatile("cp.async.cg.shared.global [%0], [%1], 16;"
                 :: "r"(dst), "l"(src) : "memory");
}
#define CP_COMMIT() asm volatile("cp.async.commit_group;" ::: "memory")
#define CP_WAIT(n)  asm volatile("cp.async.wait_group %0;" :: "n"(n) : "memory")

#define LDSM4(r0, r1, r2, r3, addr) \
    asm volatile("ldmatrix.sync.aligned.m8n8.x4.shared.b16 {%0,%1,%2,%3}, [%4];" \
                 : "=r"(r0), "=r"(r1), "=r"(r2), "=r"(r3) : "r"(addr))

#define MMA16816(d, a, b0, b1) \
    asm volatile("mma.sync.aligned.m16n8k16.row.col.f32.bf16.bf16.f32 " \
                 "{%0,%1,%2,%3}, {%4,%5,%6,%7}, {%8,%9}, {%0,%1,%2,%3};" \
                 : "+f"((d)[0]), "+f"((d)[1]), "+f"((d)[2]), "+f"((d)[3]) \
                 : "r"((a)[0]), "r"((a)[1]), "r"((a)[2]), "r"((a)[3]), \
                   "r"(b0), "r"(b1))

// ---------------------------------------------------------------------------
// Stage loader: 4 matrices x 128 rows x 8 x 16B units; 256 threads, 16 cp16
// per thread, one commit group.
// ---------------------------------------------------------------------------
__device__ __forceinline__ void load_stage(
    uint32_t base, int kc,
    const __nv_bfloat16* __restrict__ Ah, const __nv_bfloat16* __restrict__ Al,
    const __nv_bfloat16* __restrict__ Bh, const __nv_bfloat16* __restrict__ Bl,
    int bm, int bn, int tid)
{
    const __nv_bfloat16* mats[4] = { Ah, Al, Bh, Bl };
    const int r0s[4] = { bm, bm, bn, bn };
    #pragma unroll
    for (int m = 0; m < 4; ++m) {
        const __nv_bfloat16* g = mats[m];
        const int r0 = r0s[m];
        #pragma unroll
        for (int it = 0; it < 4; ++it) {
            const int u = it * 256 + tid;        // 0..1023
            const int row = u >> 3, cc = u & 7;
            cp16(base + m * TILEB + row * ROWB + cc * 16,
                 g + (size_t)(r0 + row) * MM + kc * BK + cc * 8);
        }
    }
    CP_COMMIT();
}

// ---------------------------------------------------------------------------
// GEMM core: C(128x128 per CTA) = alpha*(A@B) + beta*Df + gamma*I
// 8 warps: wr = wid&3 (4 x 32-row bands), wc = wid>>2 (2 x 64-col bands).
// ---------------------------------------------------------------------------
__device__ void gemm_core(
    const __nv_bfloat16* __restrict__ Ah, const __nv_bfloat16* __restrict__ Al,
    const __nv_bfloat16* __restrict__ Bh, const __nv_bfloat16* __restrict__ Bl,
    float* __restrict__ Cf, __nv_bfloat16* __restrict__ Chi,
    __nv_bfloat16* __restrict__ Clo, const float* __restrict__ Df,
    float alpha, float beta, float gamma)
{
    extern __shared__ char smem[];
    const int tid  = threadIdx.x;
    const int wid  = tid >> 5, lane = tid & 31;
    const int wr   = wid & 3;          // warp row: 4 x 32 rows
    const int wc   = wid >> 2;         // warp col: 2 x 64 cols
    const int bm   = blockIdx.y * BM;
    const int bn   = blockIdx.x * BN;
    const uint32_t sb = smem_u32(smem);

    float acc[2][8][4];
    #pragma unroll
    for (int mt = 0; mt < 2; ++mt)
        #pragma unroll
        for (int nt = 0; nt < 8; ++nt)
            #pragma unroll
            for (int q = 0; q < 4; ++q) acc[mt][nt][q] = 0.0f;

    // Hoisted ldmatrix offsets (row within band, k-half byte offset)
    const int lrow = lane & 15;
    const int kh16 = (lane >> 4) * 16;
    uint32_t aoff[2], boff[4];
    #pragma unroll
    for (int t = 0; t < 2; ++t)
        aoff[t] = (uint32_t)((wr * 32 + t * 16 + lrow) * ROWB + kh16);
    #pragma unroll
    for (int t = 0; t < 4; ++t)
        boff[t] = (uint32_t)((wc * 64 + t * 16 + lrow) * ROWB + kh16);

    load_stage(sb, 0, Ah, Al, Bh, Bl, bm, bn, tid);

    for (int c = 0; c < NCH; ++c) {
        const int s = c & 1;
        if (c + 1 < NCH) {
            load_stage(sb + ((c + 1) & 1) * STAGEB, c + 1, Ah, Al, Bh, Bl, bm, bn, tid);
            CP_WAIT(1);
        } else {
            CP_WAIT(0);
        }
        __syncthreads();

        const uint32_t stage = sb + s * STAGEB;
        #pragma unroll
        for (int k16 = 0; k16 < 4; ++k16) {
            const uint32_t kb = k16 * 32;
            uint32_t ah[2][4], al[2][4], bh[4][4], bl[4][4];
            #pragma unroll
            for (int t = 0; t < 2; ++t) {
                const uint32_t ra = stage + aoff[t] + kb;
                LDSM4(ah[t][0], ah[t][1], ah[t][2], ah[t][3], ra);
                LDSM4(al[t][0], al[t][1], al[t][2], al[t][3], ra + TILEB);
            }
            #pragma unroll
            for (int t = 0; t < 4; ++t) {
                const uint32_t rb = stage + boff[t] + kb;
                LDSM4(bh[t][0], bh[t][1], bh[t][2], bh[t][3], rb + 2 * TILEB);
                LDSM4(bl[t][0], bl[t][1], bl[t][2], bl[t][3], rb + 3 * TILEB);
            }
            // p-outer: 16 independent accumulator chains per pass, so
            // consecutive (volatile) MMAs never share an accumulator.
            #pragma unroll
            for (int p = 0; p < 3; ++p)
                #pragma unroll
                for (int mt = 0; mt < 2; ++mt)
                    #pragma unroll
                    for (int nt = 0; nt < 8; ++nt) {
                        const int n2 = nt >> 1, w = nt & 1;
                        if (p == 0)
                            MMA16816(acc[mt][nt], ah[mt], bh[n2][w], bh[n2][w + 2]);
                        else if (p == 1)
                            MMA16816(acc[mt][nt], ah[mt], bl[n2][w], bl[n2][w + 2]);
                        else
                            MMA16816(acc[mt][nt], al[mt], bh[n2][w], bh[n2][w + 2]);
                    }
        }
        __syncthreads();
    }

    // Epilogue: frag (mt,nt) half h -> row bm+wr*32+mt*16+(lane>>2)+h*8,
    //                                  col bn+wc*64+nt*8+(lane&3)*2
    #pragma unroll
    for (int mt = 0; mt < 2; ++mt)
        #pragma unroll
        for (int h = 0; h < 2; ++h) {
            const int r = bm + wr * 32 + mt * 16 + (lane >> 2) + h * 8;
            #pragma unroll
            for (int nt = 0; nt < 8; ++nt) {
                const int col = bn + wc * 64 + nt * 8 + (lane & 3) * 2;
                const size_t go = (size_t)r * MM + col;
                float v0 = alpha * acc[mt][nt][h * 2 + 0];
                float v1 = alpha * acc[mt][nt][h * 2 + 1];
                if (Df != nullptr) {
                    float2 d = *(const float2*)(Df + go);
                    v0 += beta * d.x;
                    v1 += beta * d.y;
                }
                if (gamma != 0.0f) {
                    if (r == col)     v0 += gamma;
                    if (r == col + 1) v1 += gamma;
                }
                if (Cf != nullptr)
                    *(float2*)(Cf + go) = make_float2(v0, v1);
                if (Chi != nullptr) {
                    __nv_bfloat16 h0 = __float2bfloat16(v0);
                    __nv_bfloat16 h1 = __float2bfloat16(v1);
                    __nv_bfloat16 l0 = __float2bfloat16(v0 - __bfloat162float(h0));
                    __nv_bfloat16 l1 = __float2bfloat16(v1 - __bfloat162float(h1));
                    __nv_bfloat162 hp; hp.x = h0; hp.y = h1;
                    __nv_bfloat162 lp; lp.x = l0; lp.y = l1;
                    *(__nv_bfloat162*)(Chi + go) = hp;
                    *(__nv_bfloat162*)(Clo + go) = lp;
                }
            }
        }
}

// ---------------------------------------------------------------------------
// Unified GEMM dispatcher.
// which: 0=T2, 1=T3, 2=T4 (z: 0 rows / 1 cols), 3=stageB (z=i-1), 4=stageC
// ---------------------------------------------------------------------------
__global__ __launch_bounds__(256)
void tc_gemm_kernel(int which, const float* __restrict__ LrF,
                    const float* __restrict__ LcF)
{
    const int z = blockIdx.z;
    const __nv_bfloat16 *Ah, *Al, *Bh, *Bl;
    float* Cf = nullptr;
    __nv_bfloat16 *Chi = nullptr, *Clo = nullptr;
    const float* Df = nullptr;
    float alpha = 1.f, beta = 0.f, gamma = 0.f;

    if (which <= 2) {
        __nv_bfloat16* Th = z ? g_Tch : g_Trh;
        __nv_bfloat16* Tl = z ? g_Tcl : g_Trl;
        const float* Lf = z ? LcF : LrF;
        Ah = Th; Al = Tl;            // A = L (hi/lo)
        alpha = 2.f;
        if (which == 0) {            // T2 = 2*L@L - I
            Bh = Th; Bl = Tl;
            gamma = -1.f;
            Cf = g_T2f + (size_t)z * PLANE;
            Chi = Th + PLANE; Clo = Tl + PLANE;
        } else if (which == 1) {     // T3 = 2*L@T2 - L
            Bh = Th + PLANE; Bl = Tl + PLANE;
            Df = Lf; beta = -1.f;
            Chi = Th + 2 * PLANE; Clo = Tl + 2 * PLANE;
        } else {                     // T4 = 2*L@T3 - T2
            Bh = Th + 2 * PLANE; Bl = Tl + 2 * PLANE;
            Df = g_T2f + (size_t)z * PLANE; beta = -1.f;
            Chi = Th + 3 * PLANE; Clo = Tl + 3 * PLANE;
        }
    } else if (which == 3) {         // Y_{z+1} = Tr_{z+1} @ X   (B = X => B^T = Xt)
        Ah = g_Trh + (size_t)z * PLANE; Al = g_Trl + (size_t)z * PLANE;
        Bh = g_Xth; Bl = g_Xtl;
        Cf  = g_Yf + (size_t)z * PLANE;
        Chi = g_Yh + (size_t)z * PLANE;
        Clo = g_Yl + (size_t)z * PLANE;
    } else {                         // Z_ij = Y_i @ Tc_j (Tc symmetric => B^T = Tc)
        const int i = z >> 2, jm = z & 3;
        Ah = i ? (g_Yh + (size_t)(i - 1) * PLANE) : g_Xh;
        Al = i ? (g_Yl + (size_t)(i - 1) * PLANE) : g_Xl;
        Bh = g_Tch + (size_t)jm * PLANE;
        Bl = g_Tcl + (size_t)jm * PLANE;
        Cf = g_Z + (size_t)z * PLANE;
    }
    gemm_core(Ah, Al, Bh, Bl, Cf, Chi, Clo, Df, alpha, beta, gamma);
}

// ---------------------------------------------------------------------------
// Split Lr/Lc into bf16 hi/lo (plane 0 of the Tr/Tc arrays).
// ---------------------------------------------------------------------------
__global__ __launch_bounds__(256)
void split_lrlc_kernel(const float* __restrict__ Lr, const float* __restrict__ Lc)
{
    const float* src = blockIdx.y ? Lc : Lr;
    __nv_bfloat16* h = blockIdx.y ? g_Tch : g_Trh;
    __nv_bfloat16* l = blockIdx.y ? g_Tcl : g_Trl;
    const size_t i4 = ((size_t)blockIdx.x * 256 + threadIdx.x) * 4;
    float4 v = *(const float4*)(src + i4);
    union { __nv_bfloat16 b[4]; float2 f; } hb, lb;
    float vv[4] = { v.x, v.y, v.z, v.w };
    #pragma unroll
    for (int j = 0; j < 4; ++j) {
        __nv_bfloat16 hh = __float2bfloat16(vv[j]);
        hb.b[j] = hh;
        lb.b[j] = __float2bfloat16(vv[j] - __bfloat162float(hh));
    }
    *(float2*)(h + i4) = hb.f;
    *(float2*)(l + i4) = lb.f;
}

// ---------------------------------------------------------------------------
// Split X (normal) + split X^T (transposed) in one pass. 32x32 tiles.
// ---------------------------------------------------------------------------
__global__ __launch_bounds__(256)
void splitX_kernel(const float* __restrict__ X)
{
    __shared__ float tile[32][33];
    const int tx = threadIdx.x, ty = threadIdx.y;   // (32, 8)
    const int bx = blockIdx.x * 32, by = blockIdx.y * 32;

    #pragma unroll
    for (int r = 0; r < 4; ++r) {
        const int y = by + ty + r * 8;
        const float v = X[(size_t)y * MM + bx + tx];
        tile[ty + r * 8][tx] = v;
        __nv_bfloat16 hh = __float2bfloat16(v);
        g_Xh[(size_t)y * MM + bx + tx] = hh;
        g_Xl[(size_t)y * MM + bx + tx] = __float2bfloat16(v - __bfloat162float(hh));
    }
    __syncthreads();
    #pragma unroll
    for (int r = 0; r < 4; ++r) {
        const float v = tile[tx][ty + r * 8];       // X[by+tx][bx+ty+r*8]
        const size_t o = (size_t)(bx + ty + r * 8) * MM + by + tx;
        __nv_bfloat16 hh = __float2bfloat16(v);
        g_Xth[o] = hh;
        g_Xtl[o] = __float2bfloat16(v - __bfloat162float(hh));
    }
}

// ---------------------------------------------------------------------------
// Combine: out[o,m,n] = bias[o] + sum_{i,j} theta[(i*5+j)*32+o] * plane_ij[m,n]
// ---------------------------------------------------------------------------
__global__ __launch_bounds__(256)
void combine_kernel(const float* __restrict__ X,
                    const float* __restrict__ theta,
                    const float* __restrict__ bias,
                    float* __restrict__ out)
{
    __shared__ float th[25][32];
    __shared__ float bs[32];

    const int tid = threadIdx.x;
    for (int t = tid; t < 25 * 32; t += blockDim.x) ((float*)th)[t] = theta[t];
    if (tid < 32) bs[tid] = bias[tid];
    __syncthreads();

    const size_t idx4 = ((size_t)blockIdx.x * blockDim.x + tid) * 4;
    if (idx4 >= PLANE) return;

    float4 v[25];
    #pragma unroll
    for (int i = 0; i < 5; i++) {
        const float* p0 = (i == 0) ? X : (g_Yf + (size_t)(i - 1) * PLANE);
        v[i * 5 + 0] = *(const float4*)&p0[idx4];
        #pragma unroll
        for (int j = 1; j < 5; j++)
            v[i * 5 + j] = *(const float4*)&g_Z[(size_t)(i * 4 + j - 1) * PLANE + idx4];
    }

    #pragma unroll
    for (int o = 0; o < 32; o++) {
        float4 s;
        s.x = s.y = s.z = s.w = bs[o];
        #pragma unroll
        for (int t = 0; t < 25; t++) {
            const float w = th[t][o];
            s.x = fmaf(w, v[t].x, s.x);
            s.y = fmaf(w, v[t].y, s.y);
            s.z = fmaf(w, v[t].z, s.z);
            s.w = fmaf(w, v[t].w, s.w);
        }
        *(float4*)&out[(size_t)o * PLANE + idx4] = s;
    }
}

// ---------------------------------------------------------------------------
// Launch
// ---------------------------------------------------------------------------
extern "C" void kernel_launch(void* const* d_in, const int* in_sizes, int n_in,
                              void* d_out, int out_size)
{
    const float* X     = (const float*)d_in[0];   // (1, M, N)
    const float* Lr    = (const float*)d_in[1];   // (M, M), symmetric
    const float* Lc    = (const float*)d_in[2];   // (N, N), symmetric
    const float* theta = (const float*)d_in[3];   // (5, 5, 1, 32)
    const float* bias  = (const float*)d_in[4];   // (32,)
    float* out = (float*)d_out;                   // (32, M, N)

    cudaFuncSetAttribute(tc_gemm_kernel,
                         cudaFuncAttributeMaxDynamicSharedMemorySize, SMEM_TOTAL);

    const dim3 blk(256);
    const int pb = (int)(PLANE / (256 * 4));      // 2304

    // Input splits
    split_lrlc_kernel<<<dim3(pb, 2), blk>>>(Lr, Lc);
    splitX_kernel<<<dim3(MM / 32, MM / 32), dim3(32, 8)>>>(X);

    // Chebyshev recursion (rows + cols batched via z; steps dependent)
    const dim3 g2(MM / BN, MM / BM, 2);
    tc_gemm_kernel<<<g2, blk, SMEM_TOTAL>>>(0, Lr, Lc);
    tc_gemm_kernel<<<g2, blk, SMEM_TOTAL>>>(1, Lr, Lc);
    tc_gemm_kernel<<<g2, blk, SMEM_TOTAL>>>(2, Lr, Lc);

    // Stage B: Y_i = Tr_i @ X
    tc_gemm_kernel<<<dim3(MM / BN, MM / BM, 4), blk, SMEM_TOTAL>>>(3, Lr, Lc);

    // Stage C: Z_ij = Y_i @ Tc_j
    tc_gemm_kernel<<<dim3(MM / BN, MM / BM, 20), blk, SMEM_TOTAL>>>(4, Lr, Lc);

    // Combine into 32 output channels
    combine_kernel<<<pb, blk>>>(X, theta, bias, out);
}

// round 10
// speedup vs baseline: 1.5542x; 1.5542x over previous
#include <cuda_runtime.h>
#include <cuda_bf16.h>
#include <cstdint>

// ============================================================================
// BilinearChebConv via mma.sync bf16-split GEMMs (compute_103-safe PTX only).
//
// out[o] = sum_{i,j} theta[i,j,o] * (Tr_i @ X @ Tc_j) + bias,
// Tr/Tc = Chebyshev bases of symmetric Lr/Lc (order 4), M = N = 1536.
//
// Every 1536^3 GEMM runs on tensor cores (mma.sync m16n8k16 bf16->fp32) with a
// 2-term bf16 split: A@B ~= Ah@Bh + Ah@Bl + Al@Bh  (error ~2^-17 per product).
// All Chebyshev matrices are symmetric => B^T = B, so both operands are fed
// K-major. Only X needs a one-time transpose (B operand of stage B).
//
// R9 = exact R6 core (BK=32, 2-stage, R6 MMA ordering) + occupancy fix:
//   - __launch_bounds__(256, 2): cap 128 regs -> 2 CTAs/SM (smem already fits)
//   - B fragments processed in two halves per k16 to keep live regs ~112
//   - non-volatile MMA asm + hoisted ldmatrix offsets
// ============================================================================

#define MM 1536
#define PLANE ((size_t)MM * MM)

#define BM 128
#define BN 128
#define BK 32
#define NCH (MM / BK)               // 48 k-chunks
#define ROWB 80                     // 32 bf16 = 64B data, padded to 80B stride
#define TILEB (128 * ROWB)          // 10240 B per matrix tile
#define STAGEB (4 * TILEB)          // Ah, Al, Bh, Bl = 40960 B
#define SMEM_TOTAL (2 * STAGEB)     // double buffered: 81920 B (2 CTAs/SM fit)

// ---------------------------------------------------------------------------
// Scratch (device globals; no runtime allocation)
// ---------------------------------------------------------------------------
__device__ __nv_bfloat16 g_Trh[4 * (size_t)MM * MM];
__device__ __nv_bfloat16 g_Trl[4 * (size_t)MM * MM];
__device__ __nv_bfloat16 g_Tch[4 * (size_t)MM * MM];
__device__ __nv_bfloat16 g_Tcl[4 * (size_t)MM * MM];
__device__ __nv_bfloat16 g_Xh [(size_t)MM * MM];
__device__ __nv_bfloat16 g_Xl [(size_t)MM * MM];
__device__ __nv_bfloat16 g_Xth[(size_t)MM * MM];
__device__ __nv_bfloat16 g_Xtl[(size_t)MM * MM];
__device__ float         g_Yf[4 * (size_t)MM * MM];
__device__ __nv_bfloat16 g_Yh[4 * (size_t)MM * MM];
__device__ __nv_bfloat16 g_Yl[4 * (size_t)MM * MM];
__device__ float g_T2f[2 * (size_t)MM * MM];
__device__ float g_Z[20 * (size_t)MM * MM];

// ---------------------------------------------------------------------------
// PTX helpers (all valid on plain compute_103)
// ---------------------------------------------------------------------------
__device__ __forceinline__ uint32_t smem_u32(const void* p) {
    uint32_t a;
    asm("{ .reg .u64 t; cvta.to.shared.u64 t, %1; cvt.u32.u64 %0, t; }"
        : "=r"(a) : "l"(p));
    return a;
}

__device__ __forceinline__ void cp16(uint32_t dst, const void* src) {
    asm volatile("cp.async.cg.shared.global [%0], [%1], 16;"
                 :: "r"(dst), "l"(src) : "memory");
}
#define CP_COMMIT() asm volatile("cp.async.commit_group;" ::: "memory")
#define CP_WAIT(n)  asm volatile("cp.async.wait_group %0;" :: "n"(n) : "memory")

#define LDSM4(r0, r1, r2, r3, addr) \
    asm volatile("ldmatrix.sync.aligned.m8n8.x4.shared.b16 {%0,%1,%2,%3}, [%4];" \
                 : "=r"(r0), "=r"(r1), "=r"(r2), "=r"(r3) : "r"(addr))

// Non-volatile: pure register computation, lets ptxas schedule freely.
#define MMA16816(d, a, b0, b1) \
    asm("mma.sync.aligned.m16n8k16.row.col.f32.bf16.bf16.f32 " \
        "{%0,%1,%2,%3}, {%4,%5,%6,%7}, {%8,%9}, {%0,%1,%2,%3};" \
        : "+f"((d)[0]), "+f"((d)[1]), "+f"((d)[2]), "+f"((d)[3]) \
        : "r"((a)[0]), "r"((a)[1]), "r"((a)[2]), "r"((a)[3]), \
          "r"(b0), "r"(b1))

// ---------------------------------------------------------------------------
// Stage loader: Ah/Al (bm rows) + Bh/Bl (bn rows), 32 bf16 of K per row,
// into 80B-strided SMEM rows. 512 x 16B chunks per matrix, 256 threads.
// ---------------------------------------------------------------------------
__device__ __forceinline__ void load_stage(
    uint32_t base, int kc,
    const __nv_bfloat16* __restrict__ Ah, const __nv_bfloat16* __restrict__ Al,
    const __nv_bfloat16* __restrict__ Bh, const __nv_bfloat16* __restrict__ Bl,
    int bm, int bn, int tid)
{
    const __nv_bfloat16* mats[4] = { Ah, Al, Bh, Bl };
    const int r0s[4] = { bm, bm, bn, bn };
    #pragma unroll
    for (int m = 0; m < 4; ++m) {
        const __nv_bfloat16* g = mats[m];
        const int r0 = r0s[m];
        #pragma unroll
        for (int it = 0; it < 2; ++it) {
            const int u = it * 256 + tid;        // 0..511
            const int row = u >> 2, cc = u & 3;
            cp16(base + m * TILEB + row * ROWB + cc * 16,
                 g + (size_t)(r0 + row) * MM + kc * BK + cc * 8);
        }
    }
    CP_COMMIT();
}

// ---------------------------------------------------------------------------
// GEMM core: C(128x128 per CTA) = alpha*(A@B) + beta*Df + gamma*I
// 8 warps: wr = wid&3 (4 x 32-row bands), wc = wid>>2 (2 x 64-col bands).
// ---------------------------------------------------------------------------
__device__ void gemm_core(
    const __nv_bfloat16* __restrict__ Ah, const __nv_bfloat16* __restrict__ Al,
    const __nv_bfloat16* __restrict__ Bh, const __nv_bfloat16* __restrict__ Bl,
    float* __restrict__ Cf, __nv_bfloat16* __restrict__ Chi,
    __nv_bfloat16* __restrict__ Clo, const float* __restrict__ Df,
    float alpha, float beta, float gamma)
{
    extern __shared__ char smem[];
    const int tid  = threadIdx.x;
    const int wid  = tid >> 5, lane = tid & 31;
    const int wr   = wid & 3;          // warp row: 4 x 32 rows
    const int wc   = wid >> 2;         // warp col: 2 x 64 cols
    const int bm   = blockIdx.y * BM;
    const int bn   = blockIdx.x * BN;
    const uint32_t sb = smem_u32(smem);

    float acc[2][8][4];
    #pragma unroll
    for (int mt = 0; mt < 2; ++mt)
        #pragma unroll
        for (int nt = 0; nt < 8; ++nt)
            #pragma unroll
            for (int q = 0; q < 4; ++q) acc[mt][nt][q] = 0.0f;

    // Hoisted ldmatrix offsets (row within band + k-half byte offset)
    const int lrow = lane & 15;
    const int kh16 = (lane >> 4) * 16;
    uint32_t aoff[2], boff[4];
    #pragma unroll
    for (int t = 0; t < 2; ++t)
        aoff[t] = (uint32_t)((wr * 32 + t * 16 + lrow) * ROWB + kh16);
    #pragma unroll
    for (int t = 0; t < 4; ++t)
        boff[t] = (uint32_t)((wc * 64 + t * 16 + lrow) * ROWB + kh16);

    load_stage(sb, 0, Ah, Al, Bh, Bl, bm, bn, tid);

    for (int c = 0; c < NCH; ++c) {
        const int s = c & 1;
        if (c + 1 < NCH) {
            load_stage(sb + ((c + 1) & 1) * STAGEB, c + 1, Ah, Al, Bh, Bl, bm, bn, tid);
            CP_WAIT(1);
        } else {
            CP_WAIT(0);
        }
        __syncthreads();

        const uint32_t stage = sb + s * STAGEB;
        #pragma unroll
        for (int k16 = 0; k16 < 2; ++k16) {
            const uint32_t kb = k16 * 32;
            uint32_t ah[2][4], al[2][4];
            #pragma unroll
            for (int t = 0; t < 2; ++t) {
                const uint32_t ra = stage + aoff[t] + kb;
                LDSM4(ah[t][0], ah[t][1], ah[t][2], ah[t][3], ra);
                LDSM4(al[t][0], al[t][1], al[t][2], al[t][3], ra + TILEB);
            }
            // Process B in two halves (cols wc*64 + half*32 .. +32) to keep
            // live registers ~112 (fits the 128-reg cap for 2 CTAs/SM).
            #pragma unroll
            for (int half = 0; half < 2; ++half) {
                uint32_t bh[2][4], bl[2][4];
                #pragma unroll
                for (int t2 = 0; t2 < 2; ++t2) {
                    const uint32_t rb = stage + boff[half * 2 + t2] + kb;
                    LDSM4(bh[t2][0], bh[t2][1], bh[t2][2], bh[t2][3],
                          rb + 2 * TILEB);
                    LDSM4(bl[t2][0], bl[t2][1], bl[t2][2], bl[t2][3],
                          rb + 3 * TILEB);
                }
                #pragma unroll
                for (int mt = 0; mt < 2; ++mt)
                    #pragma unroll
                    for (int nt4 = 0; nt4 < 4; ++nt4) {
                        const int n2 = nt4 >> 1, w = nt4 & 1;
                        float* a4 = acc[mt][half * 4 + nt4];
                        MMA16816(a4, ah[mt], bh[n2][w], bh[n2][w + 2]);
                        MMA16816(a4, ah[mt], bl[n2][w], bl[n2][w + 2]);
                        MMA16816(a4, al[mt], bh[n2][w], bh[n2][w + 2]);
                    }
            }
        }
        __syncthreads();
    }

    // Epilogue: frag (mt,nt) half h -> row bm+wr*32+mt*16+(lane>>2)+h*8,
    //                                  col bn+wc*64+nt*8+(lane&3)*2
    #pragma unroll
    for (int mt = 0; mt < 2; ++mt)
        #pragma unroll
        for (int h = 0; h < 2; ++h) {
            const int r = bm + wr * 32 + mt * 16 + (lane >> 2) + h * 8;
            #pragma unroll
            for (int nt = 0; nt < 8; ++nt) {
                const int col = bn + wc * 64 + nt * 8 + (lane & 3) * 2;
                const size_t go = (size_t)r * MM + col;
                float v0 = alpha * acc[mt][nt][h * 2 + 0];
                float v1 = alpha * acc[mt][nt][h * 2 + 1];
                if (Df != nullptr) {
                    float2 d = *(const float2*)(Df + go);
                    v0 += beta * d.x;
                    v1 += beta * d.y;
                }
                if (gamma != 0.0f) {
                    if (r == col)     v0 += gamma;
                    if (r == col + 1) v1 += gamma;
                }
                if (Cf != nullptr)
                    *(float2*)(Cf + go) = make_float2(v0, v1);
                if (Chi != nullptr) {
                    __nv_bfloat16 h0 = __float2bfloat16(v0);
                    __nv_bfloat16 h1 = __float2bfloat16(v1);
                    __nv_bfloat16 l0 = __float2bfloat16(v0 - __bfloat162float(h0));
                    __nv_bfloat16 l1 = __float2bfloat16(v1 - __bfloat162float(h1));
                    __nv_bfloat162 hp; hp.x = h0; hp.y = h1;
                    __nv_bfloat162 lp; lp.x = l0; lp.y = l1;
                    *(__nv_bfloat162*)(Chi + go) = hp;
                    *(__nv_bfloat162*)(Clo + go) = lp;
                }
            }
        }
}

// ---------------------------------------------------------------------------
// Unified GEMM dispatcher.
// which: 0=T2, 1=T3, 2=T4 (z: 0 rows / 1 cols), 3=stageB (z=i-1), 4=stageC
// ---------------------------------------------------------------------------
__global__ __launch_bounds__(256, 2)
void tc_gemm_kernel(int which, const float* __restrict__ LrF,
                    const float* __restrict__ LcF)
{
    const int z = blockIdx.z;
    const __nv_bfloat16 *Ah, *Al, *Bh, *Bl;
    float* Cf = nullptr;
    __nv_bfloat16 *Chi = nullptr, *Clo = nullptr;
    const float* Df = nullptr;
    float alpha = 1.f, beta = 0.f, gamma = 0.f;

    if (which <= 2) {
        __nv_bfloat16* Th = z ? g_Tch : g_Trh;
        __nv_bfloat16* Tl = z ? g_Tcl : g_Trl;
        const float* Lf = z ? LcF : LrF;
        Ah = Th; Al = Tl;            // A = L (hi/lo)
        alpha = 2.f;
        if (which == 0) {            // T2 = 2*L@L - I
            Bh = Th; Bl = Tl;
            gamma = -1.f;
            Cf = g_T2f + (size_t)z * PLANE;
            Chi = Th + PLANE; Clo = Tl + PLANE;
        } else if (which == 1) {     // T3 = 2*L@T2 - L
            Bh = Th + PLANE; Bl = Tl + PLANE;
            Df = Lf; beta = -1.f;
            Chi = Th + 2 * PLANE; Clo = Tl + 2 * PLANE;
        } else {                     // T4 = 2*L@T3 - T2
            Bh = Th + 2 * PLANE; Bl = Tl + 2 * PLANE;
            Df = g_T2f + (size_t)z * PLANE; beta = -1.f;
            Chi = Th + 3 * PLANE; Clo = Tl + 3 * PLANE;
        }
    } else if (which == 3) {         // Y_{z+1} = Tr_{z+1} @ X   (B = X => B^T = Xt)
        Ah = g_Trh + (size_t)z * PLANE; Al = g_Trl + (size_t)z * PLANE;
        Bh = g_Xth; Bl = g_Xtl;
        Cf  = g_Yf + (size_t)z * PLANE;
        Chi = g_Yh + (size_t)z * PLANE;
        Clo = g_Yl + (size_t)z * PLANE;
    } else {                         // Z_ij = Y_i @ Tc_j (Tc symmetric => B^T = Tc)
        const int i = z >> 2, jm = z & 3;
        Ah = i ? (g_Yh + (size_t)(i - 1) * PLANE) : g_Xh;
        Al = i ? (g_Yl + (size_t)(i - 1) * PLANE) : g_Xl;
        Bh = g_Tch + (size_t)jm * PLANE;
        Bl = g_Tcl + (size_t)jm * PLANE;
        Cf = g_Z + (size_t)z * PLANE;
    }
    gemm_core(Ah, Al, Bh, Bl, Cf, Chi, Clo, Df, alpha, beta, gamma);
}

// ---------------------------------------------------------------------------
// Split Lr/Lc into bf16 hi/lo (plane 0 of the Tr/Tc arrays).
// ---------------------------------------------------------------------------
__global__ __launch_bounds__(256)
void split_lrlc_kernel(const float* __restrict__ Lr, const float* __restrict__ Lc)
{
    const float* src = blockIdx.y ? Lc : Lr;
    __nv_bfloat16* h = blockIdx.y ? g_Tch : g_Trh;
    __nv_bfloat16* l = blockIdx.y ? g_Tcl : g_Trl;
    const size_t i4 = ((size_t)blockIdx.x * 256 + threadIdx.x) * 4;
    float4 v = *(const float4*)(src + i4);
    union { __nv_bfloat16 b[4]; float2 f; } hb, lb;
    float vv[4] = { v.x, v.y, v.z, v.w };
    #pragma unroll
    for (int j = 0; j < 4; ++j) {
        __nv_bfloat16 hh = __float2bfloat16(vv[j]);
        hb.b[j] = hh;
        lb.b[j] = __float2bfloat16(vv[j] - __bfloat162float(hh));
    }
    *(float2*)(h + i4) = hb.f;
    *(float2*)(l + i4) = lb.f;
}

// ---------------------------------------------------------------------------
// Split X (normal) + split X^T (transposed) in one pass. 32x32 tiles.
// ---------------------------------------------------------------------------
__global__ __launch_bounds__(256)
void splitX_kernel(const float* __restrict__ X)
{
    __shared__ float tile[32][33];
    const int tx = threadIdx.x, ty = threadIdx.y;   // (32, 8)
    const int bx = blockIdx.x * 32, by = blockIdx.y * 32;

    #pragma unroll
    for (int r = 0; r < 4; ++r) {
        const int y = by + ty + r * 8;
        const float v = X[(size_t)y * MM + bx + tx];
        tile[ty + r * 8][tx] = v;
        __nv_bfloat16 hh = __float2bfloat16(v);
        g_Xh[(size_t)y * MM + bx + tx] = hh;
        g_Xl[(size_t)y * MM + bx + tx] = __float2bfloat16(v - __bfloat162float(hh));
    }
    __syncthreads();
    #pragma unroll
    for (int r = 0; r < 4; ++r) {
        const float v = tile[tx][ty + r * 8];       // X[by+tx][bx+ty+r*8]
        const size_t o = (size_t)(bx + ty + r * 8) * MM + by + tx;
        __nv_bfloat16 hh = __float2bfloat16(v);
        g_Xth[o] = hh;
        g_Xtl[o] = __float2bfloat16(v - __bfloat162float(hh));
    }
}

// ---------------------------------------------------------------------------
// Combine: out[o,m,n] = bias[o] + sum_{i,j} theta[(i*5+j)*32+o] * plane_ij[m,n]
// ---------------------------------------------------------------------------
__global__ __launch_bounds__(256)
void combine_kernel(const float* __restrict__ X,
                    const float* __restrict__ theta,
                    const float* __restrict__ bias,
                    float* __restrict__ out)
{
    __shared__ float th[25][32];
    __shared__ float bs[32];

    const int tid = threadIdx.x;
    for (int t = tid; t < 25 * 32; t += blockDim.x) ((float*)th)[t] = theta[t];
    if (tid < 32) bs[tid] = bias[tid];
    __syncthreads();

    const size_t idx4 = ((size_t)blockIdx.x * blockDim.x + tid) * 4;
    if (idx4 >= PLANE) return;

    float4 v[25];
    #pragma unroll
    for (int i = 0; i < 5; i++) {
        const float* p0 = (i == 0) ? X : (g_Yf + (size_t)(i - 1) * PLANE);
        v[i * 5 + 0] = *(const float4*)&p0[idx4];
        #pragma unroll
        for (int j = 1; j < 5; j++)
            v[i * 5 + j] = *(const float4*)&g_Z[(size_t)(i * 4 + j - 1) * PLANE + idx4];
    }

    #pragma unroll
    for (int o = 0; o < 32; o++) {
        float4 s;
        s.x = s.y = s.z = s.w = bs[o];
        #pragma unroll
        for (int t = 0; t < 25; t++) {
            const float w = th[t][o];
            s.x = fmaf(w, v[t].x, s.x);
            s.y = fmaf(w, v[t].y, s.y);
            s.z = fmaf(w, v[t].z, s.z);
            s.w = fmaf(w, v[t].w, s.w);
        }
        *(float4*)&out[(size_t)o * PLANE + idx4] = s;
    }
}

// ---------------------------------------------------------------------------
// Launch
// ---------------------------------------------------------------------------
extern "C" void kernel_launch(void* const* d_in, const int* in_sizes, int n_in,
                              void* d_out, int out_size)
{
    const float* X     = (const float*)d_in[0];   // (1, M, N)
    const float* Lr    = (const float*)d_in[1];   // (M, M), symmetric
    const float* Lc    = (const float*)d_in[2];   // (N, N), symmetric
    const float* theta = (const float*)d_in[3];   // (5, 5, 1, 32)
    const float* bias  = (const float*)d_in[4];   // (32,)
    float* out = (float*)d_out;                   // (32, M, N)

    cudaFuncSetAttribute(tc_gemm_kernel,
                         cudaFuncAttributeMaxDynamicSharedMemorySize, SMEM_TOTAL);

    const dim3 blk(256);
    const int pb = (int)(PLANE / (256 * 4));      // 2304

    // Input splits
    split_lrlc_kernel<<<dim3(pb, 2), blk>>>(Lr, Lc);
    splitX_kernel<<<dim3(MM / 32, MM / 32), dim3(32, 8)>>>(X);

    // Chebyshev recursion (rows + cols batched via z; steps dependent)
    const dim3 g2(MM / BN, MM / BM, 2);
    tc_gemm_kernel<<<g2, blk, SMEM_TOTAL>>>(0, Lr, Lc);
    tc_gemm_kernel<<<g2, blk, SMEM_TOTAL>>>(1, Lr, Lc);
    tc_gemm_kernel<<<g2, blk, SMEM_TOTAL>>>(2, Lr, Lc);

    // Stage B: Y_i = Tr_i @ X
    tc_gemm_kernel<<<dim3(MM / BN, MM / BM, 4), blk, SMEM_TOTAL>>>(3, Lr, Lc);

    // Stage C: Z_ij = Y_i @ Tc_j
    tc_gemm_kernel<<<dim3(MM / BN, MM / BM, 20), blk, SMEM_TOTAL>>>(4, Lr, Lc);

    // Combine into 32 output channels
    combine_kernel<<<pb, blk>>>(X, theta, bias, out);
}

// round 13
// speedup vs baseline: 2.4410x; 1.5706x over previous
#include <cuda_runtime.h>
#include <cuda_fp16.h>
#include <cstdint>

// ============================================================================
// BilinearChebConv via mma.sync fp16-split GEMMs (compute_103-safe PTX only).
//
// out[o] = sum_{i,j} theta[i,j,o] * (Tr_i @ X @ Tc_j) + bias,
// Tr/Tc = Chebyshev bases of symmetric Lr/Lc (order 4), M = N = 1536.
//
// Tensor cores via mma.sync m16n8k16 fp16->fp32.
//  - cheb + stage B: 2-term fp16 split, 3 passes (err ~2^-21, cascade-safe)
//  - stage C (final GEMM, no cascade): single fp16 pass (err RMS ~4e-4 < 1e-3)
// All Chebyshev matrices are symmetric => B^T = B; only X needs a transpose.
//
// R11 = R9 core (BK=32, 2-stage cp.async, 2 CTAs/SM, B-halves) with fp16 and
// a single-pass stage C kernel (gemm_core<1>): 90 -> 50 pass-planes.
// ============================================================================

#define MM 1536
#define PLANE ((size_t)MM * MM)

#define BM 128
#define BN 128
#define BK 32
#define NCH (MM / BK)               // 48 k-chunks
#define ROWB 80                     // 32 fp16 = 64B data, padded to 80B stride
#define TILEB (128 * ROWB)          // 10240 B per matrix tile
#define SMEM3 (2 * 4 * TILEB)       // 3-pass: Ah,Al,Bh,Bl double-buffered
#define SMEM1 (2 * 2 * TILEB)       // 1-pass: Ah,Bh double-buffered

// ---------------------------------------------------------------------------
// Scratch (device globals; no runtime allocation)
// ---------------------------------------------------------------------------
__device__ __half g_Trh[4 * (size_t)MM * MM];   // plane 0 = Lr, 1..3 = T2..T4
__device__ __half g_Trl[4 * (size_t)MM * MM];
__device__ __half g_Tch[4 * (size_t)MM * MM];
__device__ __half g_Tcl[4 * (size_t)MM * MM];
__device__ __half g_Xh [(size_t)MM * MM];       // fp16(X)  (stage C, i=0)
__device__ __half g_Xth[(size_t)MM * MM];       // X^T hi/lo (stage B B operand)
__device__ __half g_Xtl[(size_t)MM * MM];
__device__ float  g_Yf[4 * (size_t)MM * MM];    // exact Y (combine input)
__device__ __half g_Yh[4 * (size_t)MM * MM];    // fp16(Y) (stage C A operand)
__device__ float  g_T2f[2 * (size_t)MM * MM];   // fp32 T2 (beta of T4 step)
__device__ float  g_Z[20 * (size_t)MM * MM];

// ---------------------------------------------------------------------------
// PTX helpers (all valid on plain compute_103)
// ---------------------------------------------------------------------------
__device__ __forceinline__ uint32_t smem_u32(const void* p) {
    uint32_t a;
    asm("{ .reg .u64 t; cvta.to.shared.u64 t, %1; cvt.u32.u64 %0, t; }"
        : "=r"(a) : "l"(p));
    return a;
}

__device__ __forceinline__ void cp16(uint32_t dst, const void* src) {
    asm volatile("cp.async.cg.shared.global [%0], [%1], 16;"
                 :: "r"(dst), "l"(src) : "memory");
}
#define CP_COMMIT() asm volatile("cp.async.commit_group;" ::: "memory")
#define CP_WAIT(n)  asm volatile("cp.async.wait_group %0;" :: "n"(n) : "memory")

#define LDSM4(r0, r1, r2, r3, addr) \
    asm volatile("ldmatrix.sync.aligned.m8n8.x4.shared.b16 {%0,%1,%2,%3}, [%4];" \
                 : "=r"(r0), "=r"(r1), "=r"(r2), "=r"(r3) : "r"(addr))

// Non-volatile: pure register computation, lets ptxas schedule freely.
#define MMA16816(d, a, b0, b1) \
    asm("mma.sync.aligned.m16n8k16.row.col.f32.f16.f16.f32 " \
        "{%0,%1,%2,%3}, {%4,%5,%6,%7}, {%8,%9}, {%0,%1,%2,%3};" \
        : "+f"((d)[0]), "+f"((d)[1]), "+f"((d)[2]), "+f"((d)[3]) \
        : "r"((a)[0]), "r"((a)[1]), "r"((a)[2]), "r"((a)[3]), \
          "r"(b0), "r"(b1))

// ---------------------------------------------------------------------------
// Stage loader. Layout: Ah@0, [Al@T], Bh@BOFF, [Bl@BOFF+T].
// 512 x 16B chunks per matrix, 256 threads.
// ---------------------------------------------------------------------------
template <bool LO>
__device__ __forceinline__ void load_stage(
    uint32_t base, int kc,
    const __half* __restrict__ Ah, const __half* __restrict__ Al,
    const __half* __restrict__ Bh, const __half* __restrict__ Bl,
    int bm, int bn, int tid)
{
    constexpr uint32_t BOFF = LO ? 2u * TILEB : 1u * TILEB;
    #pragma unroll
    for (int it = 0; it < 2; ++it) {
        const int u = it * 256 + tid;        // 0..511
        const int row = u >> 2, cc = u & 3;
        const uint32_t so = base + row * ROWB + cc * 16;
        const size_t ga = (size_t)(bm + row) * MM + kc * BK + cc * 8;
        const size_t gb = (size_t)(bn + row) * MM + kc * BK + cc * 8;
        cp16(so, Ah + ga);
        cp16(so + BOFF, Bh + gb);
        if (LO) {
            cp16(so + TILEB, Al + ga);
            cp16(so + BOFF + TILEB, Bl + gb);
        }
    }
    CP_COMMIT();
}

// ---------------------------------------------------------------------------
// GEMM core: C(128x128 per CTA) = alpha*(A@B) + beta*Df + gamma*I
// 8 warps: wr = wid&3 (4 x 32-row bands), wc = wid>>2 (2 x 64-col bands).
// NPASS = 3: Ah@Bh + Ah@Bl + Al@Bh.  NPASS = 1: Ah@Bh only.
// ---------------------------------------------------------------------------
template <int NPASS>
__device__ void gemm_core(
    const __half* __restrict__ Ah, const __half* __restrict__ Al,
    const __half* __restrict__ Bh, const __half* __restrict__ Bl,
    float* __restrict__ Cf, __half* __restrict__ Chi,
    __half* __restrict__ Clo, const float* __restrict__ Df,
    float alpha, float beta, float gamma)
{
    constexpr bool LO = (NPASS == 3);
    constexpr uint32_t BOFF = LO ? 2u * TILEB : 1u * TILEB;
    constexpr uint32_t STG  = LO ? 4u * TILEB : 2u * TILEB;

    extern __shared__ char smem[];
    const int tid  = threadIdx.x;
    const int wid  = tid >> 5, lane = tid & 31;
    const int wr   = wid & 3;          // warp row: 4 x 32 rows
    const int wc   = wid >> 2;         // warp col: 2 x 64 cols
    const int bm   = blockIdx.y * BM;
    const int bn   = blockIdx.x * BN;
    const uint32_t sb = smem_u32(smem);

    float acc[2][8][4];
    #pragma unroll
    for (int mt = 0; mt < 2; ++mt)
        #pragma unroll
        for (int nt = 0; nt < 8; ++nt)
            #pragma unroll
            for (int q = 0; q < 4; ++q) acc[mt][nt][q] = 0.0f;

    // Hoisted ldmatrix offsets (row within band + k-half byte offset)
    const int lrow = lane & 15;
    const int kh16 = (lane >> 4) * 16;
    uint32_t aoff[2], boff[4];
    #pragma unroll
    for (int t = 0; t < 2; ++t)
        aoff[t] = (uint32_t)((wr * 32 + t * 16 + lrow) * ROWB + kh16);
    #pragma unroll
    for (int t = 0; t < 4; ++t)
        boff[t] = (uint32_t)((wc * 64 + t * 16 + lrow) * ROWB + kh16);

    load_stage<LO>(sb, 0, Ah, Al, Bh, Bl, bm, bn, tid);

    for (int c = 0; c < NCH; ++c) {
        const int s = c & 1;
        if (c + 1 < NCH) {
            load_stage<LO>(sb + ((c + 1) & 1) * STG, c + 1, Ah, Al, Bh, Bl,
                           bm, bn, tid);
            CP_WAIT(1);
        } else {
            CP_WAIT(0);
        }
        __syncthreads();

        const uint32_t stage = sb + s * STG;
        #pragma unroll
        for (int k16 = 0; k16 < 2; ++k16) {
            const uint32_t kb = k16 * 32;
            uint32_t ah[2][4], al[2][4];
            #pragma unroll
            for (int t = 0; t < 2; ++t) {
                const uint32_t ra = stage + aoff[t] + kb;
                LDSM4(ah[t][0], ah[t][1], ah[t][2], ah[t][3], ra);
                if (LO)
                    LDSM4(al[t][0], al[t][1], al[t][2], al[t][3], ra + TILEB);
            }
            // B in two halves to keep live registers under the 128-reg cap.
            #pragma unroll
            for (int half = 0; half < 2; ++half) {
                uint32_t bh[2][4], bl[2][4];
                #pragma unroll
                for (int t2 = 0; t2 < 2; ++t2) {
                    const uint32_t rb = stage + BOFF + boff[half * 2 + t2] + kb;
                    LDSM4(bh[t2][0], bh[t2][1], bh[t2][2], bh[t2][3], rb);
                    if (LO)
                        LDSM4(bl[t2][0], bl[t2][1], bl[t2][2], bl[t2][3],
                              rb + TILEB);
                }
                #pragma unroll
                for (int mt = 0; mt < 2; ++mt)
                    #pragma unroll
                    for (int nt4 = 0; nt4 < 4; ++nt4) {
                        const int n2 = nt4 >> 1, w = nt4 & 1;
                        float* a4 = acc[mt][half * 4 + nt4];
                        MMA16816(a4, ah[mt], bh[n2][w], bh[n2][w + 2]);
                        if (LO) {
                            MMA16816(a4, ah[mt], bl[n2][w], bl[n2][w + 2]);
                            MMA16816(a4, al[mt], bh[n2][w], bh[n2][w + 2]);
                        }
                    }
            }
        }
        __syncthreads();
    }

    // Epilogue: frag (mt,nt) half h -> row bm+wr*32+mt*16+(lane>>2)+h*8,
    //                                  col bn+wc*64+nt*8+(lane&3)*2
    #pragma unroll
    for (int mt = 0; mt < 2; ++mt)
        #pragma unroll
        for (int h = 0; h < 2; ++h) {
            const int r = bm + wr * 32 + mt * 16 + (lane >> 2) + h * 8;
            #pragma unroll
            for (int nt = 0; nt < 8; ++nt) {
                const int col = bn + wc * 64 + nt * 8 + (lane & 3) * 2;
                const size_t go = (size_t)r * MM + col;
                float v0 = alpha * acc[mt][nt][h * 2 + 0];
                float v1 = alpha * acc[mt][nt][h * 2 + 1];
                if (Df != nullptr) {
                    float2 d = *(const float2*)(Df + go);
                    v0 += beta * d.x;
                    v1 += beta * d.y;
                }
                if (gamma != 0.0f) {
                    if (r == col)     v0 += gamma;
                    if (r == col + 1) v1 += gamma;
                }
                if (Cf != nullptr)
                    *(float2*)(Cf + go) = make_float2(v0, v1);
                if (Chi != nullptr) {
                    __half h0 = __float2half(v0);
                    __half h1 = __float2half(v1);
                    __half2 hp; hp.x = h0; hp.y = h1;
                    *(__half2*)(Chi + go) = hp;
                    if (Clo != nullptr) {
                        __half2 lp;
                        lp.x = __float2half(v0 - __half2float(h0));
                        lp.y = __float2half(v1 - __half2float(h1));
                        *(__half2*)(Clo + go) = lp;
                    }
                }
            }
        }
}

// ---------------------------------------------------------------------------
// 3-pass dispatcher: which: 0=T2, 1=T3, 2=T4 (z: 0 rows / 1 cols), 3=stageB
// ---------------------------------------------------------------------------
__global__ __launch_bounds__(256, 2)
void tc_gemm_kernel(int which, const float* __restrict__ LrF,
                    const float* __restrict__ LcF)
{
    const int z = blockIdx.z;
    const __half *Ah, *Al, *Bh, *Bl;
    float* Cf = nullptr;
    __half *Chi = nullptr, *Clo = nullptr;
    const float* Df = nullptr;
    float alpha = 1.f, beta = 0.f, gamma = 0.f;

    if (which <= 2) {
        __half* Th = z ? g_Tch : g_Trh;
        __half* Tl = z ? g_Tcl : g_Trl;
        const float* Lf = z ? LcF : LrF;
        Ah = Th; Al = Tl;            // A = L (hi/lo)
        alpha = 2.f;
        if (which == 0) {            // T2 = 2*L@L - I
            Bh = Th; Bl = Tl;
            gamma = -1.f;
            Cf = g_T2f + (size_t)z * PLANE;
            Chi = Th + PLANE; Clo = Tl + PLANE;
        } else if (which == 1) {     // T3 = 2*L@T2 - L
            Bh = Th + PLANE; Bl = Tl + PLANE;
            Df = Lf; beta = -1.f;
            Chi = Th + 2 * PLANE; Clo = Tl + 2 * PLANE;
        } else {                     // T4 = 2*L@T3 - T2
            Bh = Th + 2 * PLANE; Bl = Tl + 2 * PLANE;
            Df = g_T2f + (size_t)z * PLANE; beta = -1.f;
            Chi = Th + 3 * PLANE; Clo = Tl + 3 * PLANE;
        }
    } else {                         // Y_{z+1} = Tr_{z+1} @ X (B = X => B^T = Xt)
        Ah = g_Trh + (size_t)z * PLANE; Al = g_Trl + (size_t)z * PLANE;
        Bh = g_Xth; Bl = g_Xtl;
        Cf  = g_Yf + (size_t)z * PLANE;
        Chi = g_Yh + (size_t)z * PLANE;   // fp16(Y) for single-pass stage C
        Clo = nullptr;
    }
    gemm_core<3>(Ah, Al, Bh, Bl, Cf, Chi, Clo, Df, alpha, beta, gamma);
}

// ---------------------------------------------------------------------------
// Stage C, single fp16 pass: Z_ij = Y_i @ Tc_j  (z = i*4 + (j-1))
// ---------------------------------------------------------------------------
__global__ __launch_bounds__(256, 2)
void tc_gemmC_kernel()
{
    const int z = blockIdx.z;
    const int i = z >> 2, jm = z & 3;
    const __half* A = i ? (g_Yh + (size_t)(i - 1) * PLANE) : g_Xh;
    const __half* B = g_Tch + (size_t)jm * PLANE;
    gemm_core<1>(A, nullptr, B, nullptr, g_Z + (size_t)z * PLANE,
                 nullptr, nullptr, nullptr, 1.f, 0.f, 0.f);
}

// ---------------------------------------------------------------------------
// Split Lr/Lc into fp16 hi/lo (plane 0 of the Tr/Tc arrays).
// ---------------------------------------------------------------------------
__global__ __launch_bounds__(256)
void split_lrlc_kernel(const float* __restrict__ Lr, const float* __restrict__ Lc)
{
    const float* src = blockIdx.y ? Lc : Lr;
    __half* h = blockIdx.y ? g_Tch : g_Trh;
    __half* l = blockIdx.y ? g_Tcl : g_Trl;
    const size_t i4 = ((size_t)blockIdx.x * 256 + threadIdx.x) * 4;
    float4 v = *(const float4*)(src + i4);
    union { __half b[4]; float2 f; } hb, lb;
    float vv[4] = { v.x, v.y, v.z, v.w };
    #pragma unroll
    for (int j = 0; j < 4; ++j) {
        __half hh = __float2half(vv[j]);
        hb.b[j] = hh;
        lb.b[j] = __float2half(vv[j] - __half2float(hh));
    }
    *(float2*)(h + i4) = hb.f;
    *(float2*)(l + i4) = lb.f;
}

// ---------------------------------------------------------------------------
// Split X: fp16 hi (normal, stage C) + fp16 hi/lo transposed (stage B).
// ---------------------------------------------------------------------------
__global__ __launch_bounds__(256)
void splitX_kernel(const float* __restrict__ X)
{
    __shared__ float tile[32][33];
    const int tx = threadIdx.x, ty = threadIdx.y;   // (32, 8)
    const int bx = blockIdx.x * 32, by = blockIdx.y * 32;

    #pragma unroll
    for (int r = 0; r < 4; ++r) {
        const int y = by + ty + r * 8;
        const float v = X[(size_t)y * MM + bx + tx];
        tile[ty + r * 8][tx] = v;
        g_Xh[(size_t)y * MM + bx + tx] = __float2half(v);
    }
    __syncthreads();
    #pragma unroll
    for (int r = 0; r < 4; ++r) {
        const float v = tile[tx][ty + r * 8];       // X[by+tx][bx+ty+r*8]
        const size_t o = (size_t)(bx + ty + r * 8) * MM + by + tx;
        __half hh = __float2half(v);
        g_Xth[o] = hh;
        g_Xtl[o] = __float2half(v - __half2float(hh));
    }
}

// ---------------------------------------------------------------------------
// Combine: out[o,m,n] = bias[o] + sum_{i,j} theta[(i*5+j)*32+o] * plane_ij[m,n]
// ---------------------------------------------------------------------------
__global__ __launch_bounds__(256)
void combine_kernel(const float* __restrict__ X,
                    const float* __restrict__ theta,
                    const float* __restrict__ bias,
                    float* __restrict__ out)
{
    __shared__ float th[25][32];
    __shared__ float bs[32];

    const int tid = threadIdx.x;
    for (int t = tid; t < 25 * 32; t += blockDim.x) ((float*)th)[t] = theta[t];
    if (tid < 32) bs[tid] = bias[tid];
    __syncthreads();

    const size_t idx4 = ((size_t)blockIdx.x * blockDim.x + tid) * 4;
    if (idx4 >= PLANE) return;

    float4 v[25];
    #pragma unroll
    for (int i = 0; i < 5; i++) {
        const float* p0 = (i == 0) ? X : (g_Yf + (size_t)(i - 1) * PLANE);
        v[i * 5 + 0] = *(const float4*)&p0[idx4];
        #pragma unroll
        for (int j = 1; j < 5; j++)
            v[i * 5 + j] = *(const float4*)&g_Z[(size_t)(i * 4 + j - 1) * PLANE + idx4];
    }

    #pragma unroll
    for (int o = 0; o < 32; o++) {
        float4 s;
        s.x = s.y = s.z = s.w = bs[o];
        #pragma unroll
        for (int t = 0; t < 25; t++) {
            const float w = th[t][o];
            s.x = fmaf(w, v[t].x, s.x);
            s.y = fmaf(w, v[t].y, s.y);
            s.z = fmaf(w, v[t].z, s.z);
            s.w = fmaf(w, v[t].w, s.w);
        }
        *(float4*)&out[(size_t)o * PLANE + idx4] = s;
    }
}

// ---------------------------------------------------------------------------
// Launch
// ---------------------------------------------------------------------------
extern "C" void kernel_launch(void* const* d_in, const int* in_sizes, int n_in,
                              void* d_out, int out_size)
{
    const float* X     = (const float*)d_in[0];   // (1, M, N)
    const float* Lr    = (const float*)d_in[1];   // (M, M), symmetric
    const float* Lc    = (const float*)d_in[2];   // (N, N), symmetric
    const float* theta = (const float*)d_in[3];   // (5, 5, 1, 32)
    const float* bias  = (const float*)d_in[4];   // (32,)
    float* out = (float*)d_out;                   // (32, M, N)

    cudaFuncSetAttribute(tc_gemm_kernel,
                         cudaFuncAttributeMaxDynamicSharedMemorySize, SMEM3);
    cudaFuncSetAttribute(tc_gemmC_kernel,
                         cudaFuncAttributeMaxDynamicSharedMemorySize, SMEM1);

    const dim3 blk(256);
    const int pb = (int)(PLANE / (256 * 4));      // 2304

    // Input splits
    split_lrlc_kernel<<<dim3(pb, 2), blk>>>(Lr, Lc);
    splitX_kernel<<<dim3(MM / 32, MM / 32), dim3(32, 8)>>>(X);

    // Chebyshev recursion (rows + cols batched via z; steps dependent)
    const dim3 g2(MM / BN, MM / BM, 2);
    tc_gemm_kernel<<<g2, blk, SMEM3>>>(0, Lr, Lc);
    tc_gemm_kernel<<<g2, blk, SMEM3>>>(1, Lr, Lc);
    tc_gemm_kernel<<<g2, blk, SMEM3>>>(2, Lr, Lc);

    // Stage B: Y_i = Tr_i @ X   (3-pass, exact-ish)
    tc_gemm_kernel<<<dim3(MM / BN, MM / BM, 4), blk, SMEM3>>>(3, Lr, Lc);

    // Stage C: Z_ij = Y_i @ Tc_j   (single fp16 pass)
    tc_gemmC_kernel<<<dim3(MM / BN, MM / BM, 20), blk, SMEM1>>>();

    // Combine into 32 output channels
    combine_kernel<<<pb, blk>>>(X, theta, bias, out);
}